// round 17
// baseline (speedup 1.0000x reference)
#include <cuda_runtime.h>
#include <cuda_fp16.h>
#include <cstdint>

#define DI __device__ __forceinline__

// ------------------------- problem sizes -------------------------
#define N_NODES_C 16384
#define N_EDGES_C 131072
#define N_GRAPHS_C 16
#define U_SZ_C 4096
#define U_RED_C 256
#define EDGE_H_C 1024
#define EDGE_OUT_C 512
#define NODE_H_C 512
#define E_HALF (N_EDGES_C / 2)

// ------------------------- device scratch -------------------------
__device__ __half g_bufA[(size_t)N_EDGES_C * EDGE_H_C];
__device__ __half g_bufB[(size_t)N_EDGES_C * EDGE_H_C];
__device__ __half g_bufC[(size_t)N_EDGES_C * NODE_H_C];   // CW-fused outputs (512-wide)
__device__ __half g_bufD[(size_t)N_EDGES_C * NODE_H_C];   // n1w1 outputs (512-wide)
__device__ __half g_oin [(size_t)N_NODES_C * NODE_H_C];
__device__ float  g_part[2 * N_NODES_C];                   // n2+final partial dots
__device__ float  g_ur  [N_GRAPHS_C * U_RED_C];

// layer-0 small-K input: [x_row(9), x_col(9), ea(1), pad->32] + per-edge graph id
__device__ __half g_e19 [(size_t)(N_EDGES_C + 256) * 32];
__device__ int    g_gedge[N_EDGES_C];

// factorization tables
__device__ float  g_ue  [N_GRAPHS_C * EDGE_H_C];          // u_r @ W_u + e_b0
__device__ float  g_un  [N_GRAPHS_C * NODE_H_C];          // u_r @ W_u2 + n2_b0
__device__ __half g_addnh[(size_t)N_NODES_C * NODE_H_C];  // fp16 row bias for n2 GEMM

// e_wf -> n1_w0 fusion tables
__device__ __half g_cw  [EDGE_H_C * NODE_H_C];            // e_wf @ n1_w0[9:521]
__device__ float  g_bb  [NODE_H_C];
__device__ __half g_pn1h[(size_t)N_NODES_C * NODE_H_C];   // fp16 bb + x[n] @ W_x (per node)
__device__ float  g_zero[NODE_H_C];

// weights packed [Kp, N] row-major fp16
__device__ __half g_w19h [32       * EDGE_H_C];
__device__ __half g_w1h  [EDGE_H_C * EDGE_H_C];
__device__ __half g_w2h  [EDGE_H_C * EDGE_H_C];
__device__ __half g_w3h  [EDGE_H_C * EDGE_H_C];
__device__ __half g_wfh  [EDGE_H_C * EDGE_OUT_C];
__device__ __half g_n1w0h[NODE_H_C * NODE_H_C];
__device__ __half g_n1w1h[NODE_H_C * NODE_H_C];
__device__ __half g_n2w0h[NODE_H_C * NODE_H_C];

__device__ int g_cnt[N_NODES_C];
__device__ int g_off[N_NODES_C + 1];
__device__ int g_cur[N_NODES_C];
__device__ int g_elist[N_EDGES_C];

// ------------------------- small helpers -------------------------
DI uint32_t smem_u32(const void* p) {
    return (uint32_t)__cvta_generic_to_shared(p);
}
DI void cp16(uint32_t dst, const void* src) {
    asm volatile("cp.async.cg.shared.global [%0], [%1], 16;\n" :: "r"(dst), "l"(src));
}
DI void cp_commit() { asm volatile("cp.async.commit_group;\n"); }
DI void cp_wait1()  { asm volatile("cp.async.wait_group 1;\n"); }

DI void ldm_x4(uint32_t addr, uint32_t& r0, uint32_t& r1, uint32_t& r2, uint32_t& r3) {
    asm volatile("ldmatrix.sync.aligned.m8n8.x4.shared.b16 {%0,%1,%2,%3}, [%4];\n"
                 : "=r"(r0), "=r"(r1), "=r"(r2), "=r"(r3) : "r"(addr));
}
DI void ldm_x4t(uint32_t addr, uint32_t& r0, uint32_t& r1, uint32_t& r2, uint32_t& r3) {
    asm volatile("ldmatrix.sync.aligned.m8n8.x4.trans.shared.b16 {%0,%1,%2,%3}, [%4];\n"
                 : "=r"(r0), "=r"(r1), "=r"(r2), "=r"(r3) : "r"(addr));
}
DI void mma16816(float* d, const uint32_t* a, const uint32_t* b) {
    asm volatile("mma.sync.aligned.m16n8k16.row.col.f32.f16.f16.f32 "
                 "{%0,%1,%2,%3}, {%4,%5,%6,%7}, {%8,%9}, {%0,%1,%2,%3};\n"
                 : "+f"(d[0]), "+f"(d[1]), "+f"(d[2]), "+f"(d[3])
                 : "r"(a[0]), "r"(a[1]), "r"(a[2]), "r"(a[3]),
                   "r"(b[0]), "r"(b[1]));
}

// --------------- weight pack: fp32 -> fp16, row permute + zero pad ---------------
struct Seg { int src0, dst0, n; };

__global__ void pack_weight(const float* __restrict__ src, __half* __restrict__ dst,
                            int N, int Kp, Seg a, Seg b, Seg c, Seg d) {
    int idx = blockIdx.x * blockDim.x + threadIdx.x;
    if (idx >= Kp * N) return;
    int r = idx / N, col = idx - r * N;
    float v = 0.f;
    if      (r >= a.dst0 && r < a.dst0 + a.n) v = src[(size_t)(a.src0 + r - a.dst0) * N + col];
    else if (r >= b.dst0 && r < b.dst0 + b.n) v = src[(size_t)(b.src0 + r - b.dst0) * N + col];
    else if (r >= c.dst0 && r < c.dst0 + c.n) v = src[(size_t)(c.src0 + r - c.dst0) * N + col];
    else if (r >= d.dst0 && r < d.dst0 + d.n) v = src[(size_t)(d.src0 + r - d.dst0) * N + col];
    dst[idx] = __float2half(v);
}

// --------------- dim reduction: u_r = u @ w_dr + b_dr (fp32, tiny) ---------------
__global__ void dimred_kernel(const float* __restrict__ u, const float* __restrict__ w,
                              const float* __restrict__ b) {
    __shared__ float red[8][32];
    int g = blockIdx.x, ct = blockIdx.y;
    int kg = threadIdx.x >> 5, cl = threadIdx.x & 31;
    int c = ct * 32 + cl;
    const float* up = u + (size_t)g * U_SZ_C + kg * 512;
    const float* wp = w + (size_t)(kg * 512) * U_RED_C + c;
    float s = 0.f;
    #pragma unroll 8
    for (int k = 0; k < 512; k++) s += up[k] * wp[(size_t)k * U_RED_C];
    red[kg][cl] = s;
    __syncthreads();
    if (kg == 0) {
        float t = b[c];
        #pragma unroll
        for (int i = 0; i < 8; i++) t += red[i][cl];
        g_ur[g * U_RED_C + c] = t;
    }
}

// --------------- bias-table precomputes -------------------------------------------
__global__ void ue_kernel(const float* __restrict__ e_w0, const float* __restrict__ e_b0) {
    int c = blockIdx.y * 256 + threadIdx.x;
    int g = blockIdx.x;
    float s = e_b0[c];
    #pragma unroll 4
    for (int j = 0; j < U_RED_C; j++)
        s += g_ur[g * U_RED_C + j] * e_w0[(size_t)(19 + j) * EDGE_H_C + c];
    g_ue[g * EDGE_H_C + c] = s;
}

__global__ void un_kernel(const float* __restrict__ n2_w0, const float* __restrict__ n2_b0) {
    int c = blockIdx.y * 256 + threadIdx.x;
    int g = blockIdx.x;
    float s = n2_b0[c];
    #pragma unroll 4
    for (int j = 0; j < U_RED_C; j++)
        s += g_ur[g * U_RED_C + j] * n2_w0[(size_t)(521 + j) * NODE_H_C + c];
    g_un[g * NODE_H_C + c] = s;
}

__global__ void addn_kernel(const float* __restrict__ x, const int* __restrict__ batch,
                            const float* __restrict__ n2_w0) {
    int c = blockIdx.x * 256 + threadIdx.x;
    int n = blockIdx.y;
    int g = batch[n];
    float s = g_un[g * NODE_H_C + c];
    #pragma unroll
    for (int j = 0; j < 9; j++)
        s += x[(size_t)n * 9 + j] * n2_w0[(size_t)j * NODE_H_C + c];
    g_addnh[(size_t)n * NODE_H_C + c] = __float2half(s);
}

__global__ void bb_kernel(const float* __restrict__ e_bf, const float* __restrict__ n1_w0,
                          const float* __restrict__ n1_b0) {
    int c = blockIdx.x * 256 + threadIdx.x;
    float s = n1_b0[c];
    #pragma unroll 4
    for (int j = 0; j < EDGE_OUT_C; j++)
        s += e_bf[j] * n1_w0[(size_t)(9 + j) * NODE_H_C + c];
    g_bb[c] = s;
}
__global__ void pn1_kernel(const float* __restrict__ x, const float* __restrict__ n1_w0) {
    int c = blockIdx.x * 256 + threadIdx.x;
    int n = blockIdx.y;
    float s = g_bb[c];
    #pragma unroll
    for (int j = 0; j < 9; j++)
        s += x[(size_t)n * 9 + j] * n1_w0[(size_t)j * NODE_H_C + c];
    g_pn1h[(size_t)n * NODE_H_C + c] = __float2half(s);
}

// --------------- build e19 (thread per edge, vectorized 64B stores) ---------------
__global__ void build_e19_kernel(const float* __restrict__ x, const float* __restrict__ ea,
                                 const int* __restrict__ ei, const int* __restrict__ batch) {
    int e = blockIdx.x * 256 + threadIdx.x;
    int r = ei[e], c = ei[N_EDGES_C + e];
    __half h[32];
    const float* xr = x + (size_t)r * 9;
    const float* xc = x + (size_t)c * 9;
    #pragma unroll
    for (int j = 0; j < 9; j++) h[j] = __float2half(xr[j]);
    #pragma unroll
    for (int j = 0; j < 9; j++) h[9 + j] = __float2half(xc[j]);
    h[18] = __float2half(ea[e]);
    #pragma unroll
    for (int j = 19; j < 32; j++) h[j] = __float2half(0.f);
    uint4* dst = reinterpret_cast<uint4*>(g_e19 + (size_t)e * 32);
    const uint4* src = reinterpret_cast<const uint4*>(h);
    dst[0] = src[0]; dst[1] = src[1]; dst[2] = src[2]; dst[3] = src[3];
    g_gedge[e] = batch[r];
}

// ------------------------- fp16 tensor-core GEMM ---------------------------------
// BMODE: 0 = column fp32 bias vector
//        2 = indexed fp32 table  bias[bidx[r]*ldc + c]
//        3 = indexed fp16 table  hbias[bidx[r]*ldc + c]
// FINAL: fused final dot — part[bn*M + r] = sum_c relu(acc + hbias[r*ldc+c]) * fw[c]
#define BM 128
#define BN 256
#define BKK 32
#define GT 256
#define STG 3
#define A_ST (BM * 40)
#define B_ST (BKK * 264)
#define GEMM_SMEM (STG * (A_ST + B_ST) * 2)

template<bool RELU, int BMODE, bool FINAL>
__global__ __launch_bounds__(GT, 1)
void gemm_kernel(const __half* __restrict__ A, int lda,
                 const __half* __restrict__ B, int ldb,
                 const float* __restrict__ bias,
                 const __half* __restrict__ hbias,
                 const float* __restrict__ fw,
                 const int* __restrict__ bidx,
                 __half* __restrict__ C, float* __restrict__ part,
                 int ldc, int K) {
    extern __shared__ __half sm[];
    __half* Asm = sm;
    __half* Bsm = sm + STG * A_ST;

    const int tid  = threadIdx.x;
    const int lane = tid & 31, warp = tid >> 5;
    const int wm = warp & 1;
    const int wn = warp >> 1;
    const int bm = blockIdx.y, bn = blockIdx.x;

    const __half* Ag = A + (size_t)bm * BM * lda;
    const __half* Bg = B + (size_t)bn * BN;

    float acc[4][8][4];
    #pragma unroll
    for (int i = 0; i < 4; i++)
        #pragma unroll
        for (int j = 0; j < 8; j++)
            #pragma unroll
            for (int k = 0; k < 4; k++) acc[i][j][k] = 0.f;

    const int KT = K / BKK;

    auto load = [&](int kt, int st) {
        __half* as = Asm + st * A_ST;
        __half* bs = Bsm + st * B_ST;
        #pragma unroll
        for (int i = 0; i < 2; i++) {
            int ch = tid + i * GT;
            int r = ch >> 2, cc = (ch & 3) << 3;
            cp16(smem_u32(as + r * 40 + cc), Ag + (size_t)r * lda + kt * BKK + cc);
        }
        #pragma unroll
        for (int i = 0; i < 4; i++) {
            int ch = tid + i * GT;
            int r = ch >> 5, cc = (ch & 31) << 3;
            cp16(smem_u32(bs + r * 264 + cc), Bg + (size_t)(kt * BKK + r) * ldb + cc);
        }
        cp_commit();
    };

    load(0, 0);
    if (KT > 1) load(1, 1);
    else        cp_commit();   // empty group keeps wait_group(1) accounting valid

    for (int kt = 0; kt < KT; kt++) {
        cp_wait1();
        __syncthreads();
        const int st = kt % 3;
        if (kt + 2 < KT) load(kt + 2, (kt + 2) % 3);
        else             cp_commit();

        #pragma unroll
        for (int ks = 0; ks < 2; ks++) {
            uint32_t afr[4][4];
            {
                const __half* as = Asm + st * A_ST;
                int row = wm * 64 + (lane & 15);
                int col = ks * 16 + (lane >> 4) * 8;
                #pragma unroll
                for (int mi = 0; mi < 4; mi++)
                    ldm_x4(smem_u32(as + (row + mi * 16) * 40 + col),
                           afr[mi][0], afr[mi][1], afr[mi][2], afr[mi][3]);
            }
            uint32_t bfr[8][2];
            {
                const __half* bs = Bsm + st * B_ST;
                int row = ks * 16 + ((lane >> 3) & 1) * 8 + (lane & 7);
                #pragma unroll
                for (int p = 0; p < 4; p++) {
                    int col = wn * 64 + p * 16 + (lane >> 4) * 8;
                    uint32_t r0, r1, r2, r3;
                    ldm_x4t(smem_u32(bs + row * 264 + col), r0, r1, r2, r3);
                    bfr[2 * p][0] = r0;     bfr[2 * p][1] = r1;
                    bfr[2 * p + 1][0] = r2; bfr[2 * p + 1][1] = r3;
                }
            }
            #pragma unroll
            for (int mi = 0; mi < 4; mi++)
                #pragma unroll
                for (int nj = 0; nj < 8; nj++)
                    mma16816(acc[mi][nj], afr[mi], bfr[nj]);
        }
    }

    int row0 = bm * BM + wm * 64;
    int col0 = bn * BN + wn * 64;

    if (!FINAL) {
        // epilogue: bias + (relu) + fp16 store
        #pragma unroll
        for (int mi = 0; mi < 4; mi++) {
            #pragma unroll
            for (int h = 0; h < 2; h++) {
                int r = row0 + mi * 16 + (lane >> 2) + h * 8;
                const float* tbf = bias;
                const __half* tbh = hbias;
                if (BMODE == 2) tbf = bias + (size_t)bidx[r] * ldc;
                if (BMODE == 3) tbh = hbias + (size_t)bidx[r] * ldc;
                #pragma unroll
                for (int nj = 0; nj < 8; nj++) {
                    int c = col0 + nj * 8 + (lane & 3) * 2;
                    float b0, b1;
                    if (BMODE == 3) { b0 = __half2float(tbh[c]); b1 = __half2float(tbh[c + 1]); }
                    else            { b0 = tbf[c];               b1 = tbf[c + 1]; }
                    float f0 = acc[mi][nj][2 * h] + b0;
                    float f1 = acc[mi][nj][2 * h + 1] + b1;
                    if (RELU) { f0 = fmaxf(f0, 0.f); f1 = fmaxf(f1, 0.f); }
                    *reinterpret_cast<__half2*>(C + (size_t)r * ldc + c) = __floats2half2_rn(f0, f1);
                }
            }
        }
    } else {
        // fused final dot: per-row partial over this CTA's 256 columns
        float s[4][2];
        #pragma unroll
        for (int mi = 0; mi < 4; mi++)
            #pragma unroll
            for (int h = 0; h < 2; h++) s[mi][h] = 0.f;

        #pragma unroll
        for (int mi = 0; mi < 4; mi++) {
            #pragma unroll
            for (int h = 0; h < 2; h++) {
                int r = row0 + mi * 16 + (lane >> 2) + h * 8;
                const __half* tbh = hbias + (size_t)r * ldc;
                #pragma unroll
                for (int nj = 0; nj < 8; nj++) {
                    int c = col0 + nj * 8 + (lane & 3) * 2;
                    float b0 = __half2float(tbh[c]);
                    float b1 = __half2float(tbh[c + 1]);
                    float f0 = fmaxf(acc[mi][nj][2 * h] + b0, 0.f);
                    float f1 = fmaxf(acc[mi][nj][2 * h + 1] + b1, 0.f);
                    s[mi][h] += f0 * fw[c] + f1 * fw[c + 1];
                }
            }
        }
        #pragma unroll
        for (int mi = 0; mi < 4; mi++)
            #pragma unroll
            for (int h = 0; h < 2; h++) {
                float v = s[mi][h];
                v += __shfl_xor_sync(~0u, v, 1);
                v += __shfl_xor_sync(~0u, v, 2);
                s[mi][h] = v;
            }
        __syncthreads();                    // cp.async drained; safe to reuse smem
        float* smf = reinterpret_cast<float*>(sm);   // [2 wm][4 wn][64 rows]
        if ((lane & 3) == 0) {
            #pragma unroll
            for (int mi = 0; mi < 4; mi++)
                #pragma unroll
                for (int h = 0; h < 2; h++)
                    smf[(wm * 4 + wn) * 64 + mi * 16 + h * 8 + (lane >> 2)] = s[mi][h];
        }
        __syncthreads();
        if (tid < 128) {
            int wmi = tid >> 6, r64 = tid & 63;
            float v = smf[(wmi * 4 + 0) * 64 + r64] + smf[(wmi * 4 + 1) * 64 + r64]
                    + smf[(wmi * 4 + 2) * 64 + r64] + smf[(wmi * 4 + 3) * 64 + r64];
            int r = bm * BM + wmi * 64 + r64;
            part[(size_t)bn * N_NODES_C + r] = v;
        }
    }
}

// --------------- scatter-mean: CSR build + gather reduce -------------------------
__global__ void zero_cnt_kernel() {
    int i = blockIdx.x * blockDim.x + threadIdx.x;
    if (i < N_NODES_C) { g_cnt[i] = 0; g_cur[i] = 0; }
}
__global__ void count_kernel(const int* __restrict__ ei) {
    int e = blockIdx.x * blockDim.x + threadIdx.x;
    if (e < N_EDGES_C) atomicAdd(&g_cnt[ei[e]], 1);
}
__global__ void scan_kernel() {
    __shared__ int ws[32];
    int t = threadIdx.x;
    int base = t * 16;
    int v[16]; int s = 0;
    #pragma unroll
    for (int i = 0; i < 16; i++) { v[i] = s; s += g_cnt[base + i]; }
    int lane = t & 31, w = t >> 5;
    int x = s;
    #pragma unroll
    for (int o = 1; o < 32; o <<= 1) { int y = __shfl_up_sync(~0u, x, o); if (lane >= o) x += y; }
    if (lane == 31) ws[w] = x;
    __syncthreads();
    if (w == 0) {
        int y = ws[lane];
        #pragma unroll
        for (int o = 1; o < 32; o <<= 1) { int z = __shfl_up_sync(~0u, y, o); if (lane >= o) y += z; }
        ws[lane] = y;
    }
    __syncthreads();
    int pre = (x - s) + (w > 0 ? ws[w - 1] : 0);
    #pragma unroll
    for (int i = 0; i < 16; i++) g_off[base + i] = pre + v[i];
    if (t == 1023) g_off[N_NODES_C] = pre + s;
}
__global__ void fill_kernel(const int* __restrict__ ei) {
    int e = blockIdx.x * blockDim.x + threadIdx.x;
    if (e < N_EDGES_C) {
        int r = ei[e];
        int p = g_off[r] + atomicAdd(&g_cur[r], 1);
        g_elist[p] = e;
    }
}
// block per node: mean over its edges of h_n (g_bufD [E,512] fp16) -> oin
__global__ void node_reduce_kernel() {
    int n = blockIdx.x;
    int t = threadIdx.x;  // 128
    int deg = g_cnt[n], start = g_off[n];
    float a0 = 0.f, a1 = 0.f, a2 = 0.f, a3 = 0.f;
    for (int i = 0; i < deg; i++) {
        int e = g_elist[start + i];
        uint2 v = *reinterpret_cast<const uint2*>(g_bufD + (size_t)e * NODE_H_C + t * 4);
        __half2 h0 = *reinterpret_cast<__half2*>(&v.x);
        __half2 h1 = *reinterpret_cast<__half2*>(&v.y);
        float2 f0 = __half22float2(h0), f1 = __half22float2(h1);
        a0 += f0.x; a1 += f0.y; a2 += f1.x; a3 += f1.y;
    }
    float inv = 1.f / (float)(deg > 0 ? deg : 1);
    __half2 o0 = __floats2half2_rn(a0 * inv, a1 * inv);
    __half2 o1 = __floats2half2_rn(a2 * inv, a3 * inv);
    uint2 ov;
    ov.x = *reinterpret_cast<uint32_t*>(&o0);
    ov.y = *reinterpret_cast<uint32_t*>(&o1);
    *reinterpret_cast<uint2*>(g_oin + (size_t)n * NODE_H_C + t * 4) = ov;
}

// --------------- sum partials + scalar bias: out[n] = p0 + p1 + b ------------------
__global__ void sum2_kernel(const float* __restrict__ b, float* __restrict__ out) {
    int n = blockIdx.x * blockDim.x + threadIdx.x;
    if (n < N_NODES_C)
        out[n] = g_part[n] + g_part[N_NODES_C + n] + b[0];
}

// ------------------------- host launcher -----------------------------------------
extern "C" void kernel_launch(void* const* d_in, const int* in_sizes, int n_in,
                              void* d_out, int out_size) {
    (void)in_sizes; (void)n_in; (void)out_size;
    const float* x      = (const float*)d_in[0];
    const float* ea     = (const float*)d_in[1];
    const float* u      = (const float*)d_in[2];
    const int*   ei     = (const int*)d_in[3];
    const int*   batch  = (const int*)d_in[4];
    const float* w_dr   = (const float*)d_in[5];
    const float* b_dr   = (const float*)d_in[6];
    const float* e_w0   = (const float*)d_in[7];
    const float* e_b0   = (const float*)d_in[8];
    const float* e_w1   = (const float*)d_in[9];
    const float* e_b1   = (const float*)d_in[10];
    const float* e_w2   = (const float*)d_in[11];
    const float* e_b2   = (const float*)d_in[12];
    const float* e_w3   = (const float*)d_in[13];
    const float* e_b3   = (const float*)d_in[14];
    const float* e_wf   = (const float*)d_in[15];
    const float* e_bf   = (const float*)d_in[16];
    const float* n1_w0  = (const float*)d_in[17];
    const float* n1_b0  = (const float*)d_in[18];
    const float* n1_w1  = (const float*)d_in[19];
    const float* n1_b1  = (const float*)d_in[20];
    const float* n2_w0  = (const float*)d_in[21];
    const float* n2_b0  = (const float*)d_in[22];
    const float* n2_w1  = (const float*)d_in[23];
    const float* n2_b1  = (const float*)d_in[24];
    float* out = (float*)d_out;

    __half *w19h, *w1h, *w2h, *w3h, *wfh, *n1w0h, *n1w1h, *n2w0h, *cw;
    __half *bufA, *bufB, *bufC, *bufD, *oin, *e19, *pn1h, *addnh;
    float  *zerov, *uef, *gpart;
    int    *gedge;
    cudaGetSymbolAddress((void**)&w19h,  g_w19h);
    cudaGetSymbolAddress((void**)&w1h,   g_w1h);
    cudaGetSymbolAddress((void**)&w2h,   g_w2h);
    cudaGetSymbolAddress((void**)&w3h,   g_w3h);
    cudaGetSymbolAddress((void**)&wfh,   g_wfh);
    cudaGetSymbolAddress((void**)&n1w0h, g_n1w0h);
    cudaGetSymbolAddress((void**)&n1w1h, g_n1w1h);
    cudaGetSymbolAddress((void**)&n2w0h, g_n2w0h);
    cudaGetSymbolAddress((void**)&cw,    g_cw);
    cudaGetSymbolAddress((void**)&bufA, g_bufA);
    cudaGetSymbolAddress((void**)&bufB, g_bufB);
    cudaGetSymbolAddress((void**)&bufC, g_bufC);
    cudaGetSymbolAddress((void**)&bufD, g_bufD);
    cudaGetSymbolAddress((void**)&oin,  g_oin);
    cudaGetSymbolAddress((void**)&e19,  g_e19);
    cudaGetSymbolAddress((void**)&pn1h, g_pn1h);
    cudaGetSymbolAddress((void**)&addnh, g_addnh);
    cudaGetSymbolAddress((void**)&zerov, g_zero);
    cudaGetSymbolAddress((void**)&uef,  g_ue);
    cudaGetSymbolAddress((void**)&gpart, g_part);
    cudaGetSymbolAddress((void**)&gedge, g_gedge);

    cudaFuncSetAttribute((const void*)gemm_kernel<true,  0, false>, cudaFuncAttributeMaxDynamicSharedMemorySize, GEMM_SMEM);
    cudaFuncSetAttribute((const void*)gemm_kernel<false, 0, false>, cudaFuncAttributeMaxDynamicSharedMemorySize, GEMM_SMEM);
    cudaFuncSetAttribute((const void*)gemm_kernel<true,  2, false>, cudaFuncAttributeMaxDynamicSharedMemorySize, GEMM_SMEM);
    cudaFuncSetAttribute((const void*)gemm_kernel<true,  3, false>, cudaFuncAttributeMaxDynamicSharedMemorySize, GEMM_SMEM);
    cudaFuncSetAttribute((const void*)gemm_kernel<true,  4, true >, cudaFuncAttributeMaxDynamicSharedMemorySize, GEMM_SMEM);

    // streams + events — SAME footprint as the R16 clean pass (2 extra streams)
    static cudaStream_t s2 = nullptr, s3 = nullptr;
    static cudaEvent_t evFork = nullptr, evUE = nullptr, evE19 = nullptr,
                       evW123 = nullptr, evJoin = nullptr, evB = nullptr, evC1 = nullptr;
    if (s2 == nullptr) {
        cudaStreamCreateWithFlags(&s2, cudaStreamNonBlocking);
        cudaStreamCreateWithFlags(&s3, cudaStreamNonBlocking);
        cudaEventCreateWithFlags(&evFork, cudaEventDisableTiming);
        cudaEventCreateWithFlags(&evUE,   cudaEventDisableTiming);
        cudaEventCreateWithFlags(&evE19,  cudaEventDisableTiming);
        cudaEventCreateWithFlags(&evW123, cudaEventDisableTiming);
        cudaEventCreateWithFlags(&evJoin, cudaEventDisableTiming);
        cudaEventCreateWithFlags(&evB,    cudaEventDisableTiming);
        cudaEventCreateWithFlags(&evC1,   cudaEventDisableTiming);
    }

    const Seg Z{0, 0, 0};
    auto gsz = [](int n) { return (n + 255) / 256; };

    // ---- fork side work off the capture origin ----
    cudaEventRecord(evFork, 0);
    cudaStreamWaitEvent(s2, evFork, 0);
    cudaStreamWaitEvent(s3, evFork, 0);

    // ---- side stream s2: l0 deps first (dimred/ue/w19), then packs, tables, CW, CSR ----
    dimred_kernel<<<dim3(16, 8), 256, 0, s2>>>(u, w_dr, b_dr);
    pack_weight<<<gsz(32 * 1024), 256, 0, s2>>>(e_w0, w19h, 1024, 32, Seg{0, 0, 19}, Z, Z, Z);
    ue_kernel<<<dim3(16, 4), 256, 0, s2>>>(e_w0, e_b0);
    cudaEventRecord(evUE, s2);
    pack_weight<<<gsz(1024 * 1024), 256, 0, s2>>>(e_w1, w1h, 1024, 1024, Seg{0, 0, 1024}, Z, Z, Z);
    pack_weight<<<gsz(1024 * 1024), 256, 0, s2>>>(e_w2, w2h, 1024, 1024, Seg{0, 0, 1024}, Z, Z, Z);
    pack_weight<<<gsz(1024 * 1024), 256, 0, s2>>>(e_w3, w3h, 1024, 1024, Seg{0, 0, 1024}, Z, Z, Z);
    cudaEventRecord(evW123, s2);
    pack_weight<<<gsz(1024 * 512),  256, 0, s2>>>(e_wf, wfh, 512, 1024, Seg{0, 0, 1024}, Z, Z, Z);
    pack_weight<<<gsz(512 * 512),   256, 0, s2>>>(n1_w0, n1w0h, 512, 512, Seg{9, 0, 512}, Z, Z, Z);
    pack_weight<<<gsz(512 * 512),   256, 0, s2>>>(n1_w1, n1w1h, 512, 512, Seg{0, 0, 512}, Z, Z, Z);
    pack_weight<<<gsz(512 * 512),   256, 0, s2>>>(n2_w0, n2w0h, 512, 512, Seg{9, 0, 512}, Z, Z, Z);
    un_kernel<<<dim3(16, 2), 256, 0, s2>>>(n2_w0, n2_b0);
    addn_kernel<<<dim3(2, N_NODES_C), 256, 0, s2>>>(x, batch, n2_w0);
    bb_kernel<<<2, 256, 0, s2>>>(e_bf, n1_w0, n1_b0);
    pn1_kernel<<<dim3(2, N_NODES_C), 256, 0, s2>>>(x, n1_w0);
    gemm_kernel<false, 0, false><<<dim3(2, 8), GT, GEMM_SMEM, s2>>>(
        wfh, 512, n1w0h, 512, zerov, nullptr, nullptr, nullptr, cw, nullptr, 512, 512);
    cudaEventRecord(evJoin, s2);
    // CSR build (only node_reduce needs it; completes long before that joins)
    zero_cnt_kernel<<<N_NODES_C / 256, 256, 0, s2>>>();
    count_kernel<<<N_EDGES_C / 256, 256, 0, s2>>>(ei);
    scan_kernel<<<1, 1024, 0, s2>>>();
    fill_kernel<<<N_EDGES_C / 256, 256, 0, s2>>>(ei);
    cudaEventRecord(evB, s2);   // CSR-ready marker

    // ---- main: e19 build prologue (thread per edge, fast) ----
    build_e19_kernel<<<N_EDGES_C / 256, 256>>>(x, ea, ei, batch);
    cudaEventRecord(evE19, 0);

    const int MT2 = E_HALF / BM;        // 512 M-tiles per chain
    const int MTN = N_NODES_C / BM;     // 128

    // per-chain GEMM sequence (c = 0 on stream 0, c = 1 on s3)
    auto run_chain = [&](cudaStream_t st, int c) {
        const size_t o32  = (size_t)c * E_HALF * 32;
        const size_t o1k  = (size_t)c * E_HALF * EDGE_H_C;
        const size_t o512 = (size_t)c * E_HALF * NODE_H_C;
        if (st != 0) cudaStreamWaitEvent(st, evE19, 0);
        cudaStreamWaitEvent(st, evUE, 0);
        gemm_kernel<true, 2, false><<<dim3(4, MT2), GT, GEMM_SMEM, st>>>(
            e19 + o32, 32, w19h, 1024, uef, nullptr, nullptr, gedge + c * E_HALF,
            bufA + o1k, nullptr, 1024, 32);
        cudaStreamWaitEvent(st, evW123, 0);
        gemm_kernel<true, 0, false><<<dim3(4, MT2), GT, GEMM_SMEM, st>>>(
            bufA + o1k, 1024, w1h, 1024, e_b1, nullptr, nullptr, nullptr,
            bufB + o1k, nullptr, 1024, 1024);
        gemm_kernel<true, 0, false><<<dim3(4, MT2), GT, GEMM_SMEM, st>>>(
            bufB + o1k, 1024, w2h, 1024, e_b2, nullptr, nullptr, nullptr,
            bufA + o1k, nullptr, 1024, 1024);
        gemm_kernel<true, 0, false><<<dim3(4, MT2), GT, GEMM_SMEM, st>>>(
            bufA + o1k, 1024, w3h, 1024, e_b3, nullptr, nullptr, nullptr,
            bufB + o1k, nullptr, 1024, 1024);
        cudaStreamWaitEvent(st, evJoin, 0);
        gemm_kernel<true, 3, false><<<dim3(2, MT2), GT, GEMM_SMEM, st>>>(
            bufB + o1k, 1024, cw, 512, nullptr, pn1h, nullptr, ei + N_EDGES_C + c * E_HALF,
            bufC + o512, nullptr, 512, 1024);
        gemm_kernel<true, 0, false><<<dim3(2, MT2), GT, GEMM_SMEM, st>>>(
            bufC + o512, 512, n1w1h, 512, n1_b1, nullptr, nullptr, nullptr,
            bufD + o512, nullptr, 512, 512);
    };

    run_chain(0, 0);
    run_chain(s3, 1);
    cudaEventRecord(evC1, s3);

    // ---- join both chains + CSR -> scatter-mean -> fused n2+final -> sum ----
    cudaStreamWaitEvent(0, evC1, 0);
    cudaStreamWaitEvent(0, evB, 0);
    node_reduce_kernel<<<N_NODES_C, 128>>>();
    gemm_kernel<true, 4, true><<<dim3(2, MTN), GT, GEMM_SMEM>>>(
        oin, 512, n2w0h, 512, nullptr, addnh, n2_w1, nullptr,
        nullptr, gpart, 512, 512);
    sum2_kernel<<<N_NODES_C / 256, 256>>>(n2_b1, out);
}